// round 15
// baseline (speedup 1.0000x reference)
#include <cuda_runtime.h>
#include <cuda_fp16.h>
#include <math.h>
#include <cstdint>

#define N_NODES 50000
#define N_EDGES 800000
#define F 128
#define BN_EPS 1e-5f
#define RRELU_SLOPE 0.2291666666666667f  // (1/8 + 1/3)/2 = 11/48

// ---------------- scratch (device globals: no allocation allowed) ----------------
__device__ float g_agg[2][(size_t)N_NODES * F];   // agg1, agg2 (written once per row)
__device__ __half g_x16[(size_t)N_NODES * F];     // fp16 copy of x (gather source)
__device__ __half g_h16[(size_t)N_NODES * F];     // raw conv1 output (pre-BN), fp16
__device__ float g_colsum[F];
__device__ float g_colsq[F];
// CSR built per call
__device__ unsigned g_deg[N_NODES];               // in-degree counts
__device__ unsigned g_row[N_NODES + 1];           // exclusive prefix (row offsets)
__device__ unsigned g_rank[N_EDGES];              // edge rank within its target
__device__ float2 g_edge[N_EDGES];                // (src bits, weight), grouped by tgt

__device__ __forceinline__ uint32_t cvt_tf32(float f) {
    uint32_t u;
    asm("cvt.rna.tf32.f32 %0, %1;" : "=r"(u) : "f"(f));
    return u;
}

__device__ __forceinline__ float4 bn_act(float4 v, float4 sc, float4 sh) {
    v.x = fmaf(v.x, sc.x, sh.x); v.y = fmaf(v.y, sc.y, sh.y);
    v.z = fmaf(v.z, sc.z, sh.z); v.w = fmaf(v.w, sc.w, sh.w);
    v.x = v.x >= 0.f ? v.x : v.x * RRELU_SLOPE;
    v.y = v.y >= 0.f ? v.y : v.y * RRELU_SLOPE;
    v.z = v.z >= 0.f ? v.z : v.z * RRELU_SLOPE;
    v.w = v.w >= 0.f ? v.w : v.w * RRELU_SLOPE;
    return v;
}

__device__ __forceinline__ float4 h4_to_f4(uint2 u) {
    float2 lo = __half22float2(*reinterpret_cast<const __half2*>(&u.x));
    float2 hi = __half22float2(*reinterpret_cast<const __half2*>(&u.y));
    return make_float4(lo.x, lo.y, hi.x, hi.y);
}

// ---------------- zero degree counts + BN stat accumulators ----------------
__global__ void k_zero() {
    int i = blockIdx.x * blockDim.x + threadIdx.x;
    for (int j = i; j < N_NODES; j += gridDim.x * blockDim.x) g_deg[j] = 0u;
    if (i < F) { g_colsum[i] = 0.f; g_colsq[i] = 0.f; }
}

// ---------------- convert x to fp16 ----------------
__global__ void k_half(const float* __restrict__ x) {
    size_t total = (size_t)N_NODES * F / 8;    // uint4 (8 halves) per iter
    for (size_t i = (size_t)blockIdx.x * blockDim.x + threadIdx.x; i < total;
         i += (size_t)gridDim.x * blockDim.x) {
        float4 a = *reinterpret_cast<const float4*>(x + i * 8);
        float4 b = *reinterpret_cast<const float4*>(x + i * 8 + 4);
        uint4 o;
        *reinterpret_cast<__half2*>(&o.x) = __floats2half2_rn(a.x, a.y);
        *reinterpret_cast<__half2*>(&o.y) = __floats2half2_rn(a.z, a.w);
        *reinterpret_cast<__half2*>(&o.z) = __floats2half2_rn(b.x, b.y);
        *reinterpret_cast<__half2*>(&o.w) = __floats2half2_rn(b.z, b.w);
        *reinterpret_cast<uint4*>(&g_x16[i * 8]) = o;
    }
}

// ---------------- histogram of targets; record per-edge rank ----------------
__global__ void k_hist(const int* __restrict__ ei) {
    int e = blockIdx.x * blockDim.x + threadIdx.x;
    if (e < N_EDGES) g_rank[e] = atomicAdd(&g_deg[__ldg(&ei[N_EDGES + e])], 1u);
}

// ---------------- single-block exclusive scan of degrees -> row offsets ----------------
__global__ void k_scan() {
    __shared__ unsigned wsum[32];
    __shared__ unsigned s_carry;
    int tid = threadIdx.x, lane = tid & 31, wid = tid >> 5;
    if (tid == 0) s_carry = 0u;
    __syncthreads();
    for (int base = 0; base < N_NODES; base += 1024) {
        int i = base + tid;
        unsigned v = (i < N_NODES) ? g_deg[i] : 0u;
        unsigned inc = v;
#pragma unroll
        for (int d = 1; d < 32; d <<= 1) {
            unsigned t = __shfl_up_sync(0xFFFFFFFFu, inc, d);
            if (lane >= d) inc += t;
        }
        if (lane == 31) wsum[wid] = inc;
        __syncthreads();
        if (wid == 0) {
            unsigned s = wsum[lane];
#pragma unroll
            for (int d = 1; d < 32; d <<= 1) {
                unsigned t = __shfl_up_sync(0xFFFFFFFFu, s, d);
                if (lane >= d) s += t;
            }
            wsum[lane] = s;
        }
        __syncthreads();
        unsigned carry = s_carry;
        unsigned excl = carry + inc - v + (wid ? wsum[wid - 1] : 0u);
        if (i < N_NODES) g_row[i] = excl;
        __syncthreads();
        if (tid == 1023) s_carry = carry + wsum[31];
        __syncthreads();
    }
    if (threadIdx.x == 0) g_row[N_NODES] = s_carry;   // == N_EDGES
}

// ---------------- permute edges into tgt-grouped slots (no atomics) ----------------
__global__ void k_permute(const int* __restrict__ ei, const float* __restrict__ ew) {
    int e = blockIdx.x * blockDim.x + threadIdx.x;
    if (e >= N_EDGES) return;
    int t = __ldg(&ei[N_EDGES + e]);
    unsigned slot = g_row[t] + g_rank[e];
    g_edge[slot] = make_float2(__int_as_float(__ldg(&ei[e])), __ldg(&ew[e]));
}

// ---------------- gather: agg[n] = sum_{e in row(n)} w_e * f(feat16[src_e]) ------------
// Warp per node; lane owns 4 features (fp16 source, fp32 accumulate).
// Layer 1 applies BN+RReLU (scale/shift computed per CTA from colsum/colsq).
__global__ void __launch_bounds__(256)
k_gather(int layer, const float* __restrict__ gamma, const float* __restrict__ beta) {
    __shared__ float s_sc[F], s_sh[F];
    int tid = threadIdx.x;
    if (layer && tid < F) {
        float mean = g_colsum[tid] / (float)N_NODES;
        float var = g_colsq[tid] / (float)N_NODES - mean * mean;
        float sc = __ldg(&gamma[tid]) * rsqrtf(var + BN_EPS);
        s_sc[tid] = sc;
        s_sh[tid] = __ldg(&beta[tid]) - mean * sc;
    }
    if (layer) __syncthreads();

    int node = blockIdx.x * 8 + (tid >> 5);
    int lane = tid & 31;
    if (node >= N_NODES) return;
    const __half* feat = layer ? g_h16 : g_x16;

    float4 sc, sh;
    if (layer) {
        sc = *reinterpret_cast<const float4*>(&s_sc[lane * 4]);
        sh = *reinterpret_cast<const float4*>(&s_sh[lane * 4]);
    }

    int e0 = g_row[node], e1 = g_row[node + 1];
    float4 acc = make_float4(0.f, 0.f, 0.f, 0.f);

    int e = e0;
    for (; e + 4 <= e1; e += 4) {
        float2 d0 = __ldg(&g_edge[e]);
        float2 d1 = __ldg(&g_edge[e + 1]);
        float2 d2 = __ldg(&g_edge[e + 2]);
        float2 d3 = __ldg(&g_edge[e + 3]);
        uint2 u0 = __ldg(reinterpret_cast<const uint2*>(feat + (size_t)__float_as_int(d0.x) * F) + lane);
        uint2 u1 = __ldg(reinterpret_cast<const uint2*>(feat + (size_t)__float_as_int(d1.x) * F) + lane);
        uint2 u2 = __ldg(reinterpret_cast<const uint2*>(feat + (size_t)__float_as_int(d2.x) * F) + lane);
        uint2 u3 = __ldg(reinterpret_cast<const uint2*>(feat + (size_t)__float_as_int(d3.x) * F) + lane);
        float4 v0 = h4_to_f4(u0), v1 = h4_to_f4(u1), v2 = h4_to_f4(u2), v3 = h4_to_f4(u3);
        if (layer) { v0 = bn_act(v0, sc, sh); v1 = bn_act(v1, sc, sh);
                     v2 = bn_act(v2, sc, sh); v3 = bn_act(v3, sc, sh); }
        acc.x = fmaf(v0.x, d0.y, acc.x); acc.y = fmaf(v0.y, d0.y, acc.y);
        acc.z = fmaf(v0.z, d0.y, acc.z); acc.w = fmaf(v0.w, d0.y, acc.w);
        acc.x = fmaf(v1.x, d1.y, acc.x); acc.y = fmaf(v1.y, d1.y, acc.y);
        acc.z = fmaf(v1.z, d1.y, acc.z); acc.w = fmaf(v1.w, d1.y, acc.w);
        acc.x = fmaf(v2.x, d2.y, acc.x); acc.y = fmaf(v2.y, d2.y, acc.y);
        acc.z = fmaf(v2.z, d2.y, acc.z); acc.w = fmaf(v2.w, d2.y, acc.w);
        acc.x = fmaf(v3.x, d3.y, acc.x); acc.y = fmaf(v3.y, d3.y, acc.y);
        acc.z = fmaf(v3.z, d3.y, acc.z); acc.w = fmaf(v3.w, d3.y, acc.w);
    }
    for (; e < e1; e++) {
        float2 d0 = __ldg(&g_edge[e]);
        uint2 u0 = __ldg(reinterpret_cast<const uint2*>(feat + (size_t)__float_as_int(d0.x) * F) + lane);
        float4 v0 = h4_to_f4(u0);
        if (layer) v0 = bn_act(v0, sc, sh);
        acc.x = fmaf(v0.x, d0.y, acc.x); acc.y = fmaf(v0.y, d0.y, acc.y);
        acc.z = fmaf(v0.z, d0.y, acc.z); acc.w = fmaf(v0.w, d0.y, acc.w);
    }
    *reinterpret_cast<float4*>(&g_agg[layer][(size_t)node * F + lane * 4]) = acc;
}

// ---------------- mma.sync tf32 fused GEMM: C = agg@Wrel^T + f(A1)@Wroot^T + bias ------
// layer 0: A1 = x (fp32); C = g_h16 (fp16) + BN column stats.
// layer 1: A1 = g_h16 (fp16, BN+RReLU applied in staging); C = out (fp32).
__global__ void __launch_bounds__(256, 2)
k_gemm_mma(int layer, const float* __restrict__ x,
           const float* __restrict__ Wrel, const float* __restrict__ Wroot,
           const float* __restrict__ bias, float* __restrict__ out,
           const float* __restrict__ gamma, const float* __restrict__ beta) {
    __shared__ uint32_t As[128][36];
    __shared__ uint32_t Bs[128][36];
    __shared__ float s_cs[8][32];
    __shared__ float s_cq[8][32];
    __shared__ float s_sc[F], s_sh[F];

    const float* A0 = &g_agg[layer][0];

    int tid = threadIdx.x;
    int lane = tid & 31, wid = tid >> 5;
    int row0 = blockIdx.x * 128;
    int mbase = (wid & 1) * 64;
    int nbase = (wid >> 1) * 32;
    int grp = lane >> 2;
    int tig = lane & 3;

    if (layer && tid < F) {
        float mean = g_colsum[tid] / (float)N_NODES;
        float var = g_colsq[tid] / (float)N_NODES - mean * mean;
        float sc = __ldg(&gamma[tid]) * rsqrtf(var + BN_EPS);
        s_sc[tid] = sc;
        s_sh[tid] = __ldg(&beta[tid]) - mean * sc;
    }
    if (layer) __syncthreads();

    float acc[4][4][4];
#pragma unroll
    for (int mt = 0; mt < 4; mt++)
#pragma unroll
        for (int nt = 0; nt < 4; nt++)
#pragma unroll
            for (int q = 0; q < 4; q++) acc[mt][nt][q] = 0.f;

#pragma unroll 1
    for (int t = 0; t < 8; t++) {
        const float* Bsrc = (t < 4) ? Wrel : Wroot;
        int koff = (t & 3) * 32;

        // stage A tile: 128 rows x 32 k
#pragma unroll
        for (int j = 0; j < 4; j++) {
            int i = tid + j * 256;
            int r = i >> 3;
            int k4 = (i & 7) << 2;
            float4 v = make_float4(0.f, 0.f, 0.f, 0.f);
            bool in = (row0 + r < N_NODES);
            if (t < 4) {
                if (in) v = *reinterpret_cast<const float4*>(A0 + (size_t)(row0 + r) * F + koff + k4);
            } else if (layer == 0) {
                if (in) v = *reinterpret_cast<const float4*>(x + (size_t)(row0 + r) * F + koff + k4);
            } else {
                if (in) {
                    uint2 u = __ldg(reinterpret_cast<const uint2*>(g_h16 + (size_t)(row0 + r) * F + koff + k4));
                    v = h4_to_f4(u);
                }
                float4 sc = *reinterpret_cast<const float4*>(&s_sc[koff + k4]);
                float4 sh = *reinterpret_cast<const float4*>(&s_sh[koff + k4]);
                v = bn_act(v, sc, sh);
            }
            uint4 u = make_uint4(cvt_tf32(v.x), cvt_tf32(v.y), cvt_tf32(v.z), cvt_tf32(v.w));
            *reinterpret_cast<uint4*>(&As[r][k4]) = u;
        }
#pragma unroll
        for (int j = 0; j < 4; j++) {
            int i = tid + j * 256;
            int r = i >> 3;
            int k4 = (i & 7) << 2;
            float4 v = *reinterpret_cast<const float4*>(Bsrc + (size_t)r * F + koff + k4);
            uint4 u = make_uint4(cvt_tf32(v.x), cvt_tf32(v.y), cvt_tf32(v.z), cvt_tf32(v.w));
            *reinterpret_cast<uint4*>(&Bs[r][k4]) = u;
        }
        __syncthreads();

#pragma unroll
        for (int ks = 0; ks < 4; ks++) {
            int k0 = ks * 8;
            uint32_t a[4][4], b[4][2];
#pragma unroll
            for (int mt = 0; mt < 4; mt++) {
                int r = mbase + mt * 16 + grp;
                a[mt][0] = As[r][k0 + tig];
                a[mt][1] = As[r + 8][k0 + tig];
                a[mt][2] = As[r][k0 + tig + 4];
                a[mt][3] = As[r + 8][k0 + tig + 4];
            }
#pragma unroll
            for (int nt = 0; nt < 4; nt++) {
                int n = nbase + nt * 8 + grp;
                b[nt][0] = Bs[n][k0 + tig];
                b[nt][1] = Bs[n][k0 + tig + 4];
            }
#pragma unroll
            for (int mt = 0; mt < 4; mt++)
#pragma unroll
                for (int nt = 0; nt < 4; nt++)
                    asm volatile(
                        "mma.sync.aligned.m16n8k8.row.col.f32.tf32.tf32.f32 "
                        "{%0,%1,%2,%3}, {%4,%5,%6,%7}, {%8,%9}, {%0,%1,%2,%3};"
                        : "+f"(acc[mt][nt][0]), "+f"(acc[mt][nt][1]),
                          "+f"(acc[mt][nt][2]), "+f"(acc[mt][nt][3])
                        : "r"(a[mt][0]), "r"(a[mt][1]), "r"(a[mt][2]), "r"(a[mt][3]),
                          "r"(b[nt][0]), "r"(b[nt][1]));
        }
        __syncthreads();
    }

    // epilogue
    float csum[4][2], csq[4][2];
#pragma unroll
    for (int nt = 0; nt < 4; nt++) {
        csum[nt][0] = csum[nt][1] = 0.f;
        csq[nt][0] = csq[nt][1] = 0.f;
    }

#pragma unroll
    for (int nt = 0; nt < 4; nt++) {
        int c = nbase + nt * 8 + tig * 2;
        float b0 = __ldg(&bias[c]);
        float b1 = __ldg(&bias[c + 1]);
#pragma unroll
        for (int mt = 0; mt < 4; mt++) {
            int r0 = row0 + mbase + mt * 16 + grp;
            int r1 = r0 + 8;
            if (r0 < N_NODES) {
                float v0 = acc[mt][nt][0] + b0;
                float v1 = acc[mt][nt][1] + b1;
                if (layer)
                    *reinterpret_cast<float2*>(out + (size_t)r0 * F + c) = make_float2(v0, v1);
                else {
                    *reinterpret_cast<__half2*>(g_h16 + (size_t)r0 * F + c) = __floats2half2_rn(v0, v1);
                    csum[nt][0] += v0; csum[nt][1] += v1;
                    csq[nt][0] += v0 * v0; csq[nt][1] += v1 * v1;
                }
            }
            if (r1 < N_NODES) {
                float v0 = acc[mt][nt][2] + b0;
                float v1 = acc[mt][nt][3] + b1;
                if (layer)
                    *reinterpret_cast<float2*>(out + (size_t)r1 * F + c) = make_float2(v0, v1);
                else {
                    *reinterpret_cast<__half2*>(g_h16 + (size_t)r1 * F + c) = __floats2half2_rn(v0, v1);
                    csum[nt][0] += v0; csum[nt][1] += v1;
                    csq[nt][0] += v0 * v0; csq[nt][1] += v1 * v1;
                }
            }
        }
    }

    if (layer == 0) {
#pragma unroll
        for (int nt = 0; nt < 4; nt++)
#pragma unroll
            for (int q = 0; q < 2; q++) {
#pragma unroll
                for (int m = 4; m <= 16; m <<= 1) {
                    csum[nt][q] += __shfl_xor_sync(0xFFFFFFFFu, csum[nt][q], m);
                    csq[nt][q]  += __shfl_xor_sync(0xFFFFFFFFu, csq[nt][q], m);
                }
            }
        if (grp == 0) {
#pragma unroll
            for (int nt = 0; nt < 4; nt++) {
                int cl = nt * 8 + tig * 2;
                s_cs[wid][cl] = csum[nt][0]; s_cs[wid][cl + 1] = csum[nt][1];
                s_cq[wid][cl] = csq[nt][0];  s_cq[wid][cl + 1] = csq[nt][1];
            }
        }
        __syncthreads();
        if (tid < 128) {
            int w0 = (tid >> 5) * 2;
            int cl = tid & 31;
            atomicAdd(&g_colsum[tid], s_cs[w0][cl] + s_cs[w0 + 1][cl]);
            atomicAdd(&g_colsq[tid], s_cq[w0][cl] + s_cq[w0 + 1][cl]);
        }
    }
}

// ---------------- launch ----------------
extern "C" void kernel_launch(void* const* d_in, const int* in_sizes, int n_in,
                              void* d_out, int out_size) {
    const float* x      = (const float*)d_in[0];
    const int*   ei     = (const int*)d_in[1];
    const float* ew     = (const float*)d_in[2];
    const float* W1rel  = (const float*)d_in[3];
    const float* b1     = (const float*)d_in[4];
    const float* W1root = (const float*)d_in[5];
    const float* gamma  = (const float*)d_in[6];
    const float* beta   = (const float*)d_in[7];
    const float* W2rel  = (const float*)d_in[8];
    const float* b2     = (const float*)d_in[9];
    const float* W2root = (const float*)d_in[10];
    float* out = (float*)d_out;

    const int GEMM_BLOCKS = (N_NODES + 127) / 128;       // 391
    const int EDGE_BLOCKS = (N_EDGES + 255) / 256;       // 3125
    const int GATH_BLOCKS = (N_NODES + 7) / 8;           // 6250

    k_zero<<<128, 256>>>();
    k_half<<<1024, 256>>>(x);
    k_hist<<<EDGE_BLOCKS, 256>>>(ei);
    k_scan<<<1, 1024>>>();
    k_permute<<<EDGE_BLOCKS, 256>>>(ei, ew);
    k_gather<<<GATH_BLOCKS, 256>>>(0, gamma, beta);                          // -> agg1
    k_gemm_mma<<<GEMM_BLOCKS, 256>>>(0, x, W1rel, W1root, b1, out, gamma, beta); // -> h16 + stats
    k_gather<<<GATH_BLOCKS, 256>>>(1, gamma, beta);                          // -> agg2 (BN+RReLU)
    k_gemm_mma<<<GEMM_BLOCKS, 256>>>(1, x, W2rel, W2root, b2, out, gamma, beta); // -> d_out
}

// round 17
// speedup vs baseline: 1.2711x; 1.2711x over previous
#include <cuda_runtime.h>
#include <math.h>
#include <cstdint>

#define N_NODES 50000
#define N_EDGES 800000
#define F 128
#define BN_EPS 1e-5f
#define RRELU_SLOPE 0.2291666666666667f  // (1/8 + 1/3)/2 = 11/48
#define SCAN_BLK 1024
#define N_CHUNK ((N_NODES + SCAN_BLK - 1) / SCAN_BLK)   // 49

// ---------------- scratch (device globals: no allocation allowed) ----------------
__device__ float g_agg[2][(size_t)N_NODES * F];   // agg1, agg2 (written once per row)
__device__ float g_h[(size_t)N_NODES * F];        // raw conv1 output (pre-BN)
__device__ float g_colsum[F];
__device__ float g_colsq[F];
// CSR built per call
__device__ unsigned g_deg[N_NODES];               // in-degree counts
__device__ unsigned g_row[N_NODES + 1];           // exclusive prefix (row offsets)
__device__ unsigned g_rank[N_EDGES];              // edge rank within its target
__device__ unsigned g_part[N_CHUNK];              // per-chunk totals
__device__ unsigned g_partoff[N_CHUNK];           // exclusive scan of chunk totals
__device__ float2 g_edge[N_EDGES];                // (src bits, weight), grouped by tgt

__device__ __forceinline__ uint32_t cvt_tf32(float f) {
    uint32_t u;
    asm("cvt.rna.tf32.f32 %0, %1;" : "=r"(u) : "f"(f));
    return u;
}

__device__ __forceinline__ float4 bn_act(float4 v, float4 sc, float4 sh) {
    v.x = fmaf(v.x, sc.x, sh.x); v.y = fmaf(v.y, sc.y, sh.y);
    v.z = fmaf(v.z, sc.z, sh.z); v.w = fmaf(v.w, sc.w, sh.w);
    v.x = v.x >= 0.f ? v.x : v.x * RRELU_SLOPE;
    v.y = v.y >= 0.f ? v.y : v.y * RRELU_SLOPE;
    v.z = v.z >= 0.f ? v.z : v.z * RRELU_SLOPE;
    v.w = v.w >= 0.f ? v.w : v.w * RRELU_SLOPE;
    return v;
}

// ---------------- zero degree counts + BN stat accumulators ----------------
__global__ void k_zero() {
    int i = blockIdx.x * blockDim.x + threadIdx.x;
    for (int j = i; j < N_NODES; j += gridDim.x * blockDim.x) g_deg[j] = 0u;
    if (i < F) { g_colsum[i] = 0.f; g_colsq[i] = 0.f; }
}

// ---------------- histogram of targets; record per-edge rank ----------------
__global__ void k_hist(const int* __restrict__ ei) {
    int e = blockIdx.x * blockDim.x + threadIdx.x;
    if (e < N_EDGES) g_rank[e] = atomicAdd(&g_deg[__ldg(&ei[N_EDGES + e])], 1u);
}

// ---------------- two-level scan: chunk scans (parallel) ----------------
__global__ void k_scan1() {
    __shared__ unsigned wsum[32];
    int tid = threadIdx.x, lane = tid & 31, wid = tid >> 5;
    int i = blockIdx.x * SCAN_BLK + tid;
    unsigned v = (i < N_NODES) ? g_deg[i] : 0u;
    unsigned inc = v;
#pragma unroll
    for (int d = 1; d < 32; d <<= 1) {
        unsigned t = __shfl_up_sync(0xFFFFFFFFu, inc, d);
        if (lane >= d) inc += t;
    }
    if (lane == 31) wsum[wid] = inc;
    __syncthreads();
    if (wid == 0) {
        unsigned s = wsum[lane];
#pragma unroll
        for (int d = 1; d < 32; d <<= 1) {
            unsigned t = __shfl_up_sync(0xFFFFFFFFu, s, d);
            if (lane >= d) s += t;
        }
        wsum[lane] = s;
    }
    __syncthreads();
    unsigned excl = inc - v + (wid ? wsum[wid - 1] : 0u);
    if (i < N_NODES) g_row[i] = excl;
    if (tid == SCAN_BLK - 1) g_part[blockIdx.x] = excl + v;
}

// ---------------- scan the 49 chunk totals (single tiny block) ----------------
__global__ void k_scan2() {
    __shared__ unsigned s_w0;
    int tid = threadIdx.x;          // 64 threads
    int lane = tid & 31, wid = tid >> 5;
    unsigned v = (tid < N_CHUNK) ? g_part[tid] : 0u;
    unsigned inc = v;
#pragma unroll
    for (int d = 1; d < 32; d <<= 1) {
        unsigned t = __shfl_up_sync(0xFFFFFFFFu, inc, d);
        if (lane >= d) inc += t;
    }
    if (wid == 0 && lane == 31) s_w0 = inc;
    __syncthreads();
    unsigned base = wid ? s_w0 : 0u;
    if (tid < N_CHUNK) g_partoff[tid] = base + inc - v;
    if (tid == N_CHUNK - 1) g_row[N_NODES] = base + inc;   // == N_EDGES
}

// ---------------- add chunk offsets ----------------
__global__ void k_scan3() {
    int i = blockIdx.x * SCAN_BLK + threadIdx.x;
    if (i < N_NODES && blockIdx.x > 0) g_row[i] += g_partoff[blockIdx.x];
}

// ---------------- permute edges into tgt-grouped slots (no atomics) ----------------
__global__ void k_permute(const int* __restrict__ ei, const float* __restrict__ ew) {
    int e = blockIdx.x * blockDim.x + threadIdx.x;
    if (e >= N_EDGES) return;
    int t = __ldg(&ei[N_EDGES + e]);
    unsigned slot = g_row[t] + g_rank[e];
    g_edge[slot] = make_float2(__int_as_float(__ldg(&ei[e])), __ldg(&ew[e]));
}

// ---------------- gather: agg[n] = sum_{e in row(n)} w_e * f(feat[src_e]) --------------
// Warp per node; lane owns 4 features. Layer 1 applies BN+RReLU (scale/shift from stats).
__global__ void __launch_bounds__(256)
k_gather(int layer, const float* __restrict__ x,
         const float* __restrict__ gamma, const float* __restrict__ beta) {
    __shared__ float s_sc[F], s_sh[F];
    int tid = threadIdx.x;
    if (layer && tid < F) {
        float mean = g_colsum[tid] / (float)N_NODES;
        float var = g_colsq[tid] / (float)N_NODES - mean * mean;
        float sc = __ldg(&gamma[tid]) * rsqrtf(var + BN_EPS);
        s_sc[tid] = sc;
        s_sh[tid] = __ldg(&beta[tid]) - mean * sc;
    }
    if (layer) __syncthreads();

    int node = blockIdx.x * 8 + (tid >> 5);
    int lane = tid & 31;
    if (node >= N_NODES) return;
    const float* feat = layer ? g_h : x;

    float4 sc, sh;
    if (layer) {
        sc = *reinterpret_cast<const float4*>(&s_sc[lane * 4]);
        sh = *reinterpret_cast<const float4*>(&s_sh[lane * 4]);
    }

    int e0 = g_row[node], e1 = g_row[node + 1];
    float4 acc = make_float4(0.f, 0.f, 0.f, 0.f);

    int e = e0;
    for (; e + 4 <= e1; e += 4) {
        float2 d0 = __ldg(&g_edge[e]);
        float2 d1 = __ldg(&g_edge[e + 1]);
        float2 d2 = __ldg(&g_edge[e + 2]);
        float2 d3 = __ldg(&g_edge[e + 3]);
        float4 v0 = __ldg(reinterpret_cast<const float4*>(feat + (size_t)__float_as_int(d0.x) * F) + lane);
        float4 v1 = __ldg(reinterpret_cast<const float4*>(feat + (size_t)__float_as_int(d1.x) * F) + lane);
        float4 v2 = __ldg(reinterpret_cast<const float4*>(feat + (size_t)__float_as_int(d2.x) * F) + lane);
        float4 v3 = __ldg(reinterpret_cast<const float4*>(feat + (size_t)__float_as_int(d3.x) * F) + lane);
        if (layer) { v0 = bn_act(v0, sc, sh); v1 = bn_act(v1, sc, sh);
                     v2 = bn_act(v2, sc, sh); v3 = bn_act(v3, sc, sh); }
        acc.x = fmaf(v0.x, d0.y, acc.x); acc.y = fmaf(v0.y, d0.y, acc.y);
        acc.z = fmaf(v0.z, d0.y, acc.z); acc.w = fmaf(v0.w, d0.y, acc.w);
        acc.x = fmaf(v1.x, d1.y, acc.x); acc.y = fmaf(v1.y, d1.y, acc.y);
        acc.z = fmaf(v1.z, d1.y, acc.z); acc.w = fmaf(v1.w, d1.y, acc.w);
        acc.x = fmaf(v2.x, d2.y, acc.x); acc.y = fmaf(v2.y, d2.y, acc.y);
        acc.z = fmaf(v2.z, d2.y, acc.z); acc.w = fmaf(v2.w, d2.y, acc.w);
        acc.x = fmaf(v3.x, d3.y, acc.x); acc.y = fmaf(v3.y, d3.y, acc.y);
        acc.z = fmaf(v3.z, d3.y, acc.z); acc.w = fmaf(v3.w, d3.y, acc.w);
    }
    for (; e < e1; e++) {
        float2 d0 = __ldg(&g_edge[e]);
        float4 v0 = __ldg(reinterpret_cast<const float4*>(feat + (size_t)__float_as_int(d0.x) * F) + lane);
        if (layer) v0 = bn_act(v0, sc, sh);
        acc.x = fmaf(v0.x, d0.y, acc.x); acc.y = fmaf(v0.y, d0.y, acc.y);
        acc.z = fmaf(v0.z, d0.y, acc.z); acc.w = fmaf(v0.w, d0.y, acc.w);
    }
    *reinterpret_cast<float4*>(&g_agg[layer][(size_t)node * F + lane * 4]) = acc;
}

// ---------------- mma.sync tf32 fused GEMM: C = agg@Wrel^T + f(A1)@Wroot^T + bias ------
// layer 0: A1 = x; C = g_h + BN column stats. layer 1: A1 = g_h with BN+RReLU; C = out.
__global__ void __launch_bounds__(256, 2)
k_gemm_mma(int layer, const float* __restrict__ x,
           const float* __restrict__ Wrel, const float* __restrict__ Wroot,
           const float* __restrict__ bias, float* __restrict__ out,
           const float* __restrict__ gamma, const float* __restrict__ beta) {
    __shared__ uint32_t As[128][36];
    __shared__ uint32_t Bs[128][36];
    __shared__ float s_cs[8][32];
    __shared__ float s_cq[8][32];
    __shared__ float s_sc[F], s_sh[F];

    const float* A0 = &g_agg[layer][0];
    const float* A1 = layer ? g_h : x;
    float* C = layer ? out : g_h;

    int tid = threadIdx.x;
    int lane = tid & 31, wid = tid >> 5;
    int row0 = blockIdx.x * 128;
    int mbase = (wid & 1) * 64;
    int nbase = (wid >> 1) * 32;
    int grp = lane >> 2;
    int tig = lane & 3;

    if (layer && tid < F) {
        float mean = g_colsum[tid] / (float)N_NODES;
        float var = g_colsq[tid] / (float)N_NODES - mean * mean;
        float sc = __ldg(&gamma[tid]) * rsqrtf(var + BN_EPS);
        s_sc[tid] = sc;
        s_sh[tid] = __ldg(&beta[tid]) - mean * sc;
    }
    if (layer) __syncthreads();

    float acc[4][4][4];
#pragma unroll
    for (int mt = 0; mt < 4; mt++)
#pragma unroll
        for (int nt = 0; nt < 4; nt++)
#pragma unroll
            for (int q = 0; q < 4; q++) acc[mt][nt][q] = 0.f;

#pragma unroll 1
    for (int t = 0; t < 8; t++) {
        const float* Asrc = (t < 4) ? A0 : A1;
        const float* Bsrc = (t < 4) ? Wrel : Wroot;
        int koff = (t & 3) * 32;
        int bn_stage = (layer != 0) && (t >= 4);

#pragma unroll
        for (int j = 0; j < 4; j++) {
            int i = tid + j * 256;
            int r = i >> 3;
            int k4 = (i & 7) << 2;
            float4 v = make_float4(0.f, 0.f, 0.f, 0.f);
            if (row0 + r < N_NODES)
                v = *reinterpret_cast<const float4*>(Asrc + (size_t)(row0 + r) * F + koff + k4);
            if (bn_stage) {
                float4 sc = *reinterpret_cast<const float4*>(&s_sc[koff + k4]);
                float4 sh = *reinterpret_cast<const float4*>(&s_sh[koff + k4]);
                v = bn_act(v, sc, sh);
            }
            uint4 u = make_uint4(cvt_tf32(v.x), cvt_tf32(v.y), cvt_tf32(v.z), cvt_tf32(v.w));
            *reinterpret_cast<uint4*>(&As[r][k4]) = u;
        }
#pragma unroll
        for (int j = 0; j < 4; j++) {
            int i = tid + j * 256;
            int r = i >> 3;
            int k4 = (i & 7) << 2;
            float4 v = *reinterpret_cast<const float4*>(Bsrc + (size_t)r * F + koff + k4);
            uint4 u = make_uint4(cvt_tf32(v.x), cvt_tf32(v.y), cvt_tf32(v.z), cvt_tf32(v.w));
            *reinterpret_cast<uint4*>(&Bs[r][k4]) = u;
        }
        __syncthreads();

#pragma unroll
        for (int ks = 0; ks < 4; ks++) {
            int k0 = ks * 8;
            uint32_t a[4][4], b[4][2];
#pragma unroll
            for (int mt = 0; mt < 4; mt++) {
                int r = mbase + mt * 16 + grp;
                a[mt][0] = As[r][k0 + tig];
                a[mt][1] = As[r + 8][k0 + tig];
                a[mt][2] = As[r][k0 + tig + 4];
                a[mt][3] = As[r + 8][k0 + tig + 4];
            }
#pragma unroll
            for (int nt = 0; nt < 4; nt++) {
                int n = nbase + nt * 8 + grp;
                b[nt][0] = Bs[n][k0 + tig];
                b[nt][1] = Bs[n][k0 + tig + 4];
            }
#pragma unroll
            for (int mt = 0; mt < 4; mt++)
#pragma unroll
                for (int nt = 0; nt < 4; nt++)
                    asm volatile(
                        "mma.sync.aligned.m16n8k8.row.col.f32.tf32.tf32.f32 "
                        "{%0,%1,%2,%3}, {%4,%5,%6,%7}, {%8,%9}, {%0,%1,%2,%3};"
                        : "+f"(acc[mt][nt][0]), "+f"(acc[mt][nt][1]),
                          "+f"(acc[mt][nt][2]), "+f"(acc[mt][nt][3])
                        : "r"(a[mt][0]), "r"(a[mt][1]), "r"(a[mt][2]), "r"(a[mt][3]),
                          "r"(b[nt][0]), "r"(b[nt][1]));
        }
        __syncthreads();
    }

    float csum[4][2], csq[4][2];
#pragma unroll
    for (int nt = 0; nt < 4; nt++) {
        csum[nt][0] = csum[nt][1] = 0.f;
        csq[nt][0] = csq[nt][1] = 0.f;
    }

#pragma unroll
    for (int nt = 0; nt < 4; nt++) {
        int c = nbase + nt * 8 + tig * 2;
        float b0 = __ldg(&bias[c]);
        float b1 = __ldg(&bias[c + 1]);
#pragma unroll
        for (int mt = 0; mt < 4; mt++) {
            int r0 = row0 + mbase + mt * 16 + grp;
            int r1 = r0 + 8;
            if (r0 < N_NODES) {
                float v0 = acc[mt][nt][0] + b0;
                float v1 = acc[mt][nt][1] + b1;
                *reinterpret_cast<float2*>(C + (size_t)r0 * F + c) = make_float2(v0, v1);
                csum[nt][0] += v0; csum[nt][1] += v1;
                csq[nt][0] += v0 * v0; csq[nt][1] += v1 * v1;
            }
            if (r1 < N_NODES) {
                float v0 = acc[mt][nt][2] + b0;
                float v1 = acc[mt][nt][3] + b1;
                *reinterpret_cast<float2*>(C + (size_t)r1 * F + c) = make_float2(v0, v1);
                csum[nt][0] += v0; csum[nt][1] += v1;
                csq[nt][0] += v0 * v0; csq[nt][1] += v1 * v1;
            }
        }
    }

    if (layer == 0) {
#pragma unroll
        for (int nt = 0; nt < 4; nt++)
#pragma unroll
            for (int q = 0; q < 2; q++) {
#pragma unroll
                for (int m = 4; m <= 16; m <<= 1) {
                    csum[nt][q] += __shfl_xor_sync(0xFFFFFFFFu, csum[nt][q], m);
                    csq[nt][q]  += __shfl_xor_sync(0xFFFFFFFFu, csq[nt][q], m);
                }
            }
        if (grp == 0) {
#pragma unroll
            for (int nt = 0; nt < 4; nt++) {
                int cl = nt * 8 + tig * 2;
                s_cs[wid][cl] = csum[nt][0]; s_cs[wid][cl + 1] = csum[nt][1];
                s_cq[wid][cl] = csq[nt][0];  s_cq[wid][cl + 1] = csq[nt][1];
            }
        }
        __syncthreads();
        if (tid < 128) {
            int w0 = (tid >> 5) * 2;
            int cl = tid & 31;
            atomicAdd(&g_colsum[tid], s_cs[w0][cl] + s_cs[w0 + 1][cl]);
            atomicAdd(&g_colsq[tid], s_cq[w0][cl] + s_cq[w0 + 1][cl]);
        }
    }
}

// ---------------- launch ----------------
extern "C" void kernel_launch(void* const* d_in, const int* in_sizes, int n_in,
                              void* d_out, int out_size) {
    const float* x      = (const float*)d_in[0];
    const int*   ei     = (const int*)d_in[1];
    const float* ew     = (const float*)d_in[2];
    const float* W1rel  = (const float*)d_in[3];
    const float* b1     = (const float*)d_in[4];
    const float* W1root = (const float*)d_in[5];
    const float* gamma  = (const float*)d_in[6];
    const float* beta   = (const float*)d_in[7];
    const float* W2rel  = (const float*)d_in[8];
    const float* b2     = (const float*)d_in[9];
    const float* W2root = (const float*)d_in[10];
    float* out = (float*)d_out;

    const int GEMM_BLOCKS = (N_NODES + 127) / 128;       // 391
    const int EDGE_BLOCKS = (N_EDGES + 255) / 256;       // 3125
    const int GATH_BLOCKS = (N_NODES + 7) / 8;           // 6250

    k_zero<<<128, 256>>>();
    k_hist<<<EDGE_BLOCKS, 256>>>(ei);
    k_scan1<<<N_CHUNK, SCAN_BLK>>>();
    k_scan2<<<1, 64>>>();
    k_scan3<<<N_CHUNK, SCAN_BLK>>>();
    k_permute<<<EDGE_BLOCKS, 256>>>(ei, ew);
    k_gather<<<GATH_BLOCKS, 256>>>(0, x, gamma, beta);                           // -> agg1
    k_gemm_mma<<<GEMM_BLOCKS, 256>>>(0, x, W1rel, W1root, b1, out, gamma, beta); // -> g_h + stats
    k_gather<<<GATH_BLOCKS, 256>>>(1, x, gamma, beta);                           // -> agg2 (BN+RReLU)
    k_gemm_mma<<<GEMM_BLOCKS, 256>>>(1, x, W2rel, W2root, b2, out, gamma, beta); // -> d_out
}